// round 5
// baseline (speedup 1.0000x reference)
#include <cuda_runtime.h>
#include <cuda_bf16.h>

// Problem constants
#define BB    32
#define NN    2048
#define KK    16
#define FIN   32
#define FOUT  64
#define TOTAL (BB * NN)          // 65536 nodes
#define ROW4  (FOUT / 4)         // 16 float4 per feature row

// Scratch (device globals: allocation-free rule). float4 arrays guarantee 16B alignment.
__device__ float4 g_a[TOTAL * ROW4];   // a_i = x_i @ (W1 - W2) + b_edge
__device__ float4 g_c[TOTAL * ROW4];   // c_j = x_j @ W2
__device__ float4 g_s[TOTAL * ROW4];   // skip_i = relu(x_i @ W_nn + b_nn)

__device__ __forceinline__ float4 f4fma(float s, float4 w, float4 a) {
    a.x = __fmaf_rn(s, w.x, a.x);
    a.y = __fmaf_rn(s, w.y, a.y);
    a.z = __fmaf_rn(s, w.z, a.z);
    a.w = __fmaf_rn(s, w.w, a.w);
    return a;
}
__device__ __forceinline__ float4 f4max(float4 a, float4 b) {
    return make_float4(fmaxf(a.x, b.x), fmaxf(a.y, b.y),
                       fmaxf(a.z, b.z), fmaxf(a.w, b.w));
}

// Squared distance with a FIXED op sequence (both KNN passes must agree bitwise).
// d2 = (sq_i + sq_j) - 2*dot, matching the reference's formulation.
__device__ __forceinline__ float dist2(float4 p, float4 q) {
    float dot = __fmaf_rn(p.x, q.x, __fmaf_rn(p.y, q.y, __fmul_rn(p.z, q.z)));
    return __fmaf_rn(-2.0f, dot, __fadd_rn(p.w, q.w));
}

// ---------------------------------------------------------------------------
// Kernel 1: per-node projections a, c, skip. One thread per node.
// Weights staged in smem; all lanes read the same (r,f) -> broadcast LDS.
// ---------------------------------------------------------------------------
__global__ __launch_bounds__(128)
void proj_kernel(const float* __restrict__ x,
                 const float* __restrict__ W_edge,
                 const float* __restrict__ b_edge,
                 const float* __restrict__ W_nn,
                 const float* __restrict__ b_nn)
{
    __shared__ float sWd[FIN * FOUT];   // W1 - W2
    __shared__ float sW2[FIN * FOUT];   // W2
    __shared__ float sWn[FIN * FOUT];   // W_nn
    __shared__ float sbe[FOUT];
    __shared__ float sbn[FOUT];

    int tid = threadIdx.x;
    for (int t = tid; t < FIN * FOUT; t += 128) {
        float w1 = W_edge[t];                 // rows 0..31   (multiply x_i)
        float w2 = W_edge[FIN * FOUT + t];    // rows 32..63  (multiply x_j - x_i)
        sWd[t] = w1 - w2;
        sW2[t] = w2;
        sWn[t] = W_nn[t];
    }
    if (tid < FOUT) { sbe[tid] = b_edge[tid]; sbn[tid] = b_nn[tid]; }
    __syncthreads();

    int node = blockIdx.x * 128 + tid;

    float xr[FIN];
    const float4* xp = (const float4*)(x + node * FIN);
#pragma unroll
    for (int q = 0; q < FIN / 4; q++) {
        float4 v = xp[q];
        xr[4 * q + 0] = v.x; xr[4 * q + 1] = v.y;
        xr[4 * q + 2] = v.z; xr[4 * q + 3] = v.w;
    }

    int rowb = node * ROW4;
#pragma unroll 1                       // keep code size inside I$ (body ~8KB)
    for (int fc = 0; fc < FOUT; fc += 4) {
        float4 aA = *(const float4*)&sbe[fc];
        float4 aC = make_float4(0.f, 0.f, 0.f, 0.f);
        float4 aS = *(const float4*)&sbn[fc];
#pragma unroll
        for (int r = 0; r < FIN; r++) {
            float xv = xr[r];
            aA = f4fma(xv, *(const float4*)&sWd[r * FOUT + fc], aA);
            aC = f4fma(xv, *(const float4*)&sW2[r * FOUT + fc], aC);
            aS = f4fma(xv, *(const float4*)&sWn[r * FOUT + fc], aS);
        }
        aS.x = fmaxf(aS.x, 0.f); aS.y = fmaxf(aS.y, 0.f);
        aS.z = fmaxf(aS.z, 0.f); aS.w = fmaxf(aS.w, 0.f);
        g_a[rowb + (fc >> 2)] = aA;
        g_c[rowb + (fc >> 2)] = aC;
        g_s[rowb + (fc >> 2)] = aS;
    }
}

// ---------------------------------------------------------------------------
// Kernel 2: brute-force exact KNN (top-16 smallest d2, lower-index tie-break)
// + neighbor c-row max-gather + epilogue. One thread per node, one batch's
// positions staged as float4 (x,y,z,|p|^2) in smem -> broadcast LDS.128.
//
// Pass 1: exact sorted-16 of DISTANCES only (FMNMX chain, no indices).
// Pass 2: recompute d2 bitwise-identically; collect j with d2 <= d16,
//         ascending j, capped at 16  == reference top_k tie-breaking.
// ---------------------------------------------------------------------------
__global__ __launch_bounds__(256)
void knn_kernel(const float* __restrict__ pos, float4* __restrict__ out)
{
    __shared__ float4 sp[NN];          // 32 KB

    int tid   = threadIdx.x;
    int batch = blockIdx.x >> 3;       // 8 blocks per batch
    int base  = batch * NN;

    for (int t = tid; t < NN; t += 256) {
        float p0 = pos[(base + t) * 3 + 0];
        float p1 = pos[(base + t) * 3 + 1];
        float p2 = pos[(base + t) * 3 + 2];
        float sq = __fmaf_rn(p0, p0, __fmaf_rn(p1, p1, __fmul_rn(p2, p2)));
        sp[t] = make_float4(p0, p1, p2, sq);
    }
    __syncthreads();

    int iLoc = ((blockIdx.x & 7) << 8) + tid;
    float4 pi = sp[iLoc];

    // ---- Pass 1: sorted-16 smallest distances (values only) ----
    float s[KK];
#pragma unroll
    for (int q = 0; q < KK; q++) s[q] = 3.0e38f;

#pragma unroll 4
    for (int j = 0; j < NN; j++) {
        float d = dist2(pi, sp[j]);
        if (d < s[KK - 1] && j != iLoc) {
            float t = d;
#pragma unroll
            for (int q = 0; q < KK; q++) {
                float lo = fminf(s[q], t);
                t        = fmaxf(s[q], t);
                s[q]     = lo;
            }
        }
    }
    float t16 = s[KK - 1];

    // ---- Pass 2: recover indices (branchless predicated collect) ----
    int nb[KK];
#pragma unroll
    for (int q = 0; q < KK; q++) nb[q] = 0;
    int cnt = 0;
#pragma unroll 4
    for (int j = 0; j < NN; j++) {
        float d = dist2(pi, sp[j]);
        if (d <= t16 && j != iLoc && cnt < KK) {
            nb[cnt] = j;               // dynamic index -> local mem, fine (16 writes)
            cnt++;
        }
    }

    int gb[KK];                        // float4 row bases of the 16 neighbors
#pragma unroll
    for (int k = 0; k < KK; k++) gb[k] = (base + nb[k]) * ROW4;

    // ---- Aggregation: cmax[f] = max_k c_jk[f]; out = relu(a+cmax)+skip ----
    int irow = (base + iLoc) * ROW4;
#pragma unroll 1
    for (int h = 0; h < ROW4; h += 4) {
        float4 m0 = make_float4(-3e38f, -3e38f, -3e38f, -3e38f);
        float4 m1 = m0, m2 = m0, m3 = m0;
#pragma unroll
        for (int k = 0; k < KK; k++) {
            const float4* cp = &g_c[gb[k] + h];
            m0 = f4max(m0, cp[0]);
            m1 = f4max(m1, cp[1]);
            m2 = f4max(m2, cp[2]);
            m3 = f4max(m3, cp[3]);
        }
        float4 mm[4] = {m0, m1, m2, m3};
#pragma unroll
        for (int u = 0; u < 4; u++) {
            float4 a = g_a[irow + h + u];
            float4 sk = g_s[irow + h + u];
            float4 o;
            o.x = fmaxf(a.x + mm[u].x, 0.f) + sk.x;
            o.y = fmaxf(a.y + mm[u].y, 0.f) + sk.y;
            o.z = fmaxf(a.z + mm[u].z, 0.f) + sk.z;
            o.w = fmaxf(a.w + mm[u].w, 0.f) + sk.w;
            out[irow + h + u] = o;
        }
    }
}

// ---------------------------------------------------------------------------
// Inputs (metadata order): x, pos, W_edge, b_edge, W_nn, b_nn, batch(unused)
// Output: float32 [65536, 64]
// ---------------------------------------------------------------------------
extern "C" void kernel_launch(void* const* d_in, const int* in_sizes, int n_in,
                              void* d_out, int out_size)
{
    const float* x      = (const float*)d_in[0];
    const float* pos    = (const float*)d_in[1];
    const float* W_edge = (const float*)d_in[2];
    const float* b_edge = (const float*)d_in[3];
    const float* W_nn   = (const float*)d_in[4];
    const float* b_nn   = (const float*)d_in[5];

    proj_kernel<<<TOTAL / 128, 128>>>(x, W_edge, b_edge, W_nn, b_nn);
    knn_kernel<<<TOTAL / 256, 256>>>(pos, (float4*)d_out);
}